// round 10
// baseline (speedup 1.0000x reference)
#include <cuda_runtime.h>
#include <stdint.h>

// Shapes (fixed):
//   updates: (32, 64, 64, 128) fp32  -> 16,777,216 elems
//   mask:    same shape, int32 in [0, 2,097,152)
//   output:  (32, 128, 128, 128) fp32 -> 67,108,864 elems (256 MB)
#define N_IN        16777216
#define FLAT_OUT    2097152      // per-batch output slots (8 MB)
#define N_OUT       67108864
#define NBATCH      32
#define BLKS_PER_B  64           // blocks per batch group (1024 threads each)
#define DELAY       2            // scatter batch = zero batch - DELAY

// Per-batch zero-completion counters (reset every launch by init kernel).
__device__ unsigned int g_ctr[NBATCH];

__global__ void init_ctr_kernel() {
    if (threadIdx.x < NBATCH) g_ctr[threadIdx.x] = 0u;
}

__device__ __forceinline__ unsigned int ld_acquire_gpu(const unsigned int* p) {
    unsigned int v;
    asm volatile("ld.acquire.gpu.global.u32 %0, [%1];" : "=r"(v) : "l"(p) : "memory");
    return v;
}

__device__ __forceinline__ void red_release_gpu_add(unsigned int* p, unsigned int v) {
    asm volatile("red.release.gpu.global.add.u32 [%0], %1;" :: "l"(p), "r"(v) : "memory");
}

// ---------------------------------------------------------------------------
// Fused zero + scatter pipeline, 1024-thread blocks, 2x work per thread
// (half the blocks of R8 -> half the publishes / acquire-poll rounds).
//   Block bid:
//     zb = bid >> 6 : zeroes a 128 KB chunk of batch zb (8 STG.128 / thread)
//     sb = zb - 2   : scatters a 8192-element chunk of batch sb (2 vec4 =
//                     8 REDs / thread) after all 64 zero-blocks of batch sb
//                     have published.
//   Register discipline: only the FIRST vec4 pair is prefetched before the
//   zero phase; the second pair loads after the first 4 REDs, keeping peak
//   live registers <= 32 so 2 CTAs/SM stay resident.
//   Producers of batch sb have strictly lower block IDs (>= 128 earlier);
//   producers never spin and CTAs dispatch in bid order with backfill ->
//   the spin cannot deadlock.
// ---------------------------------------------------------------------------
__global__ void __launch_bounds__(1024, 2) fused_unpool_kernel(
    const float4* __restrict__ upd,
    const int4*   __restrict__ mask,
    float*        __restrict__ out)
{
    const int bid = blockIdx.x;
    const int t   = threadIdx.x;                // 0..1023
    const int zb  = bid >> 6;                   // batch to zero
    const int c   = bid & (BLKS_PER_B - 1);     // chunk within group
    const int sb  = zb - DELAY;                 // batch to scatter

    const bool do_scatter = (sb >= 0) && (sb < NBATCH);

    // Base vec4 index of this block's 2048-vec4 scatter chunk.
    const int vi = (sb << 17) + (c << 11) + t;

    // Prefetch FIRST scatter pair (streaming: one-shot input read must not
    // evict the zeroed output window from L2).
    float4 u0 = make_float4(0.f, 0.f, 0.f, 0.f);
    int4   m0 = make_int4(0, 0, 0, 0);
    if (do_scatter) {
        u0 = __ldcs(&upd[vi]);
        m0 = __ldcs(&mask[vi]);
    }

    // ---- zero phase: 128 KB = 8192 float4, 8 per thread, coalesced ----
    if (zb < NBATCH) {
        float4* zp = reinterpret_cast<float4*>(out) +
                     ((size_t)zb << 19) + (c << 13) + t;    // FLAT_OUT/4 = 2^19
        const float4 z = make_float4(0.f, 0.f, 0.f, 0.f);
        #pragma unroll
        for (int k = 0; k < 8; k++) zp[k << 10] = z;

        __syncthreads();               // BAR.SYNC drains pending stores (HW)
        if (t == 0) red_release_gpu_add(&g_ctr[zb], 1u);    // publish
    }

    if (!do_scatter) return;

    // ---- wait until batch sb is fully zeroed (acquire-poll, 1 thread) ----
    if (t == 0) {
        if (ld_acquire_gpu(&g_ctr[sb]) < BLKS_PER_B) {
            do { __nanosleep(32); } while (ld_acquire_gpu(&g_ctr[sb]) < BLKS_PER_B);
        }
    }
    __syncthreads();   // broadcast the acquire to the whole CTA

    float* ob = out + ((size_t)sb << 21);                   // FLAT_OUT = 2^21

    // ---- scatter first vec4 (prefetched) ----
    atomicAdd(ob + m0.x, u0.x);
    atomicAdd(ob + m0.y, u0.y);
    atomicAdd(ob + m0.z, u0.z);
    atomicAdd(ob + m0.w, u0.w);

    // ---- load + scatter second vec4 (latency hidden by resident warps) ----
    float4 u1 = __ldcs(&upd[vi + 1024]);
    int4   m1 = __ldcs(&mask[vi + 1024]);
    atomicAdd(ob + m1.x, u1.x);
    atomicAdd(ob + m1.y, u1.y);
    atomicAdd(ob + m1.z, u1.z);
    atomicAdd(ob + m1.w, u1.w);
}

extern "C" void kernel_launch(void* const* d_in, const int* in_sizes, int n_in,
                              void* d_out, int out_size)
{
    const float4* upd  = (const float4*)d_in[0];
    const int4*   mask = (const int4*)  d_in[1];
    float*        out  = (float*)d_out;

    init_ctr_kernel<<<1, 32>>>();

    // 32 zero-groups * 64 blocks + DELAY*64 scatter-only tail blocks.
    const int grid = (NBATCH + DELAY) * BLKS_PER_B;   // 2176
    fused_unpool_kernel<<<grid, 1024>>>(upd, mask, out);
}

// round 11
// speedup vs baseline: 1.2366x; 1.2366x over previous
#include <cuda_runtime.h>
#include <stdint.h>

// Shapes (fixed):
//   updates: (32, 64, 64, 128) fp32  -> 16,777,216 elems
//   mask:    same shape, int32 in [0, 2,097,152)
//   output:  (32, 128, 128, 128) fp32 -> 67,108,864 elems (256 MB)
#define N_IN        16777216
#define FLAT_OUT    2097152      // per-batch output slots (8 MB)
#define N_OUT       67108864
#define NBATCH      32
#define BLKS_PER_B  128          // blocks per batch group (1024 threads each)
#define DELAY       1            // scatter batch = zero batch - DELAY

// Per-batch zero-completion counters (reset every launch by init kernel).
__device__ unsigned int g_ctr[NBATCH];

__global__ void init_ctr_kernel() {
    if (threadIdx.x < NBATCH) g_ctr[threadIdx.x] = 0u;
}

__device__ __forceinline__ unsigned int ld_acquire_gpu(const unsigned int* p) {
    unsigned int v;
    asm volatile("ld.acquire.gpu.global.u32 %0, [%1];" : "=r"(v) : "l"(p) : "memory");
    return v;
}

__device__ __forceinline__ void red_release_gpu_add(unsigned int* p, unsigned int v) {
    asm volatile("red.release.gpu.global.add.u32 [%0], %1;" :: "l"(p), "r"(v) : "memory");
}

// ---------------------------------------------------------------------------
// Fused zero + scatter pipeline (R8 configuration, DELAY=1).
//   Block bid (1024 threads):
//     zb = bid >> 7 : zeroes a 64 KB chunk of batch zb's output (zb < 32)
//     sb = zb - 1   : scatters a 4096-element input chunk of batch sb after
//                     all 128 zero-blocks of batch sb have published.
//   One vec4 per thread: the scatter is a pure fire-and-forget RED burst
//   (no mid-scatter loads — R9's regression), regs <= 32 so 2 CTAs/SM.
//   Producers of batch sb have strictly lower block IDs (>= 128 earlier);
//   producers never spin; CTAs dispatch in bid order with backfill -> the
//   spin cannot deadlock. Each consumer zeroes its own chunk before waiting,
//   giving the prior group the whole zero phase to finish -> rare spins.
//   BAR.SYNC drains the zero STGs (HW-native on B300); one elected thread
//   publishes with red.release.gpu; consumers poll with ld.acquire.gpu.
//   Scatter REDs then RMW lines that are still L2-resident (R8 measured
//   exactly the mandatory 384 MB of DRAM traffic).
// ---------------------------------------------------------------------------
__global__ void __launch_bounds__(1024) fused_unpool_kernel(
    const float4* __restrict__ upd,
    const int4*   __restrict__ mask,
    float*        __restrict__ out)
{
    const int bid = blockIdx.x;
    const int t   = threadIdx.x;                // 0..1023
    const int zb  = bid >> 7;                   // batch to zero
    const int c   = bid & (BLKS_PER_B - 1);     // chunk within group
    const int sb  = zb - DELAY;                 // batch to scatter

    const bool do_scatter = (sb >= 0) && (sb < NBATCH);

    // Prefetch scatter inputs (streaming / evict-first: the one-shot 128 MB
    // input read must not evict the zeroed output window from L2).
    float4 u = make_float4(0.f, 0.f, 0.f, 0.f);
    int4   m = make_int4(0, 0, 0, 0);
    if (do_scatter) {
        const int vi = (sb << 17) + (c << 10) + t;  // vec4 index within batch
        u = __ldcs(&upd[vi]);
        m = __ldcs(&mask[vi]);
    }

    // ---- zero phase: 64 KB = 4096 float4, 4 per thread, coalesced ----
    if (zb < NBATCH) {
        float4* zp = reinterpret_cast<float4*>(out) +
                     ((size_t)zb << 19) + (c << 12) + t;    // FLAT_OUT/4 = 2^19
        const float4 z = make_float4(0.f, 0.f, 0.f, 0.f);
        zp[0]    = z;
        zp[1024] = z;
        zp[2048] = z;
        zp[3072] = z;

        __syncthreads();               // BAR.SYNC drains pending stores (HW)
        if (t == 0) red_release_gpu_add(&g_ctr[zb], 1u);    // publish
    }

    if (!do_scatter) return;

    // ---- wait until batch sb is fully zeroed (acquire-poll, 1 thread) ----
    if (t == 0) {
        if (ld_acquire_gpu(&g_ctr[sb]) < BLKS_PER_B) {
            do { __nanosleep(32); } while (ld_acquire_gpu(&g_ctr[sb]) < BLKS_PER_B);
        }
    }
    __syncthreads();   // broadcast the acquire to the whole CTA

    // ---- scatter phase: 4 fire-and-forget REDs into the L2-warm window ----
    float* ob = out + ((size_t)sb << 21);                   // FLAT_OUT = 2^21
    atomicAdd(ob + m.x, u.x);
    atomicAdd(ob + m.y, u.y);
    atomicAdd(ob + m.z, u.z);
    atomicAdd(ob + m.w, u.w);
}

extern "C" void kernel_launch(void* const* d_in, const int* in_sizes, int n_in,
                              void* d_out, int out_size)
{
    const float4* upd  = (const float4*)d_in[0];
    const int4*   mask = (const int4*)  d_in[1];
    float*        out  = (float*)d_out;

    init_ctr_kernel<<<1, 32>>>();

    // 32 zero-groups * 128 blocks + DELAY*128 scatter-only tail blocks.
    const int grid = (NBATCH + DELAY) * BLKS_PER_B;   // 4224
    fused_unpool_kernel<<<grid, 1024>>>(upd, mask, out);
}